// round 6
// baseline (speedup 1.0000x reference)
#include <cuda_runtime.h>

// ---------------------------------------------------------------------------
// DNN_SKalmanNet_GSS — batch-1 GEMV chain, HBM-bound (~499 MB weights/pass).
// 4 launches:
//   K1: input built in smem + l1/l3 GEMV (relu)            [~46 MB]  R=4
//   K2: GRU gi/gh GEMV, 4 segments                         [~352 MB] R=4
//   K3: GRU gate fused into staging + W1 GEMV (relu)       [~67 MB]  R=4
//   K4: W2 GEMV -> d_out                                   [~34 MB]  R=2
// gemv_core<R>: each warp owns R rows (row_r = warp + r*nw). Register
// double-buffer prefetch of next j-step's R weight vectors -> guaranteed
// R loads in flight (ptxas cannot serialize: no dependency on current FMAs).
// One smem x read feeds all R rows.
// ---------------------------------------------------------------------------

#define H1   5120
#define H2   4096
#define HID  2048
#define IN1  1120

__device__ float g_l1[H1];
__device__ float g_l3[H1];
__device__ float g_gi1[3 * HID];
__device__ float g_gh1[3 * HID];
__device__ float g_gi2[3 * HID];
__device__ float g_gh2[3 * HID];
__device__ float g_hid1[H2];
__device__ float g_hid2[H2];

// Requires: rows == R * nw (grid sized accordingly).
template <int R>
__device__ __forceinline__ void gemv_core(const float* __restrict__ W,
                                          const float* __restrict__ b,
                                          float* __restrict__ y,
                                          int c4, int act,
                                          const float4* __restrict__ sx) {
    const int lane = threadIdx.x & 31;
    const int warp = (blockIdx.x * blockDim.x + threadIdx.x) >> 5;
    const int nw   = (gridDim.x * blockDim.x) >> 5;

    const float4* Wr[R];
    float acc[R];
    #pragma unroll
    for (int r = 0; r < R; r++) {
        Wr[r]  = (const float4*)W + (size_t)(warp + r * nw) * c4;
        acc[r] = 0.f;
    }

    const float4 f4z = make_float4(0.f, 0.f, 0.f, 0.f);
    float4 w[R], wn[R];
    int j = lane;
    #pragma unroll
    for (int r = 0; r < R; r++)
        w[r] = (j < c4) ? Wr[r][j] : f4z;

    while (j < c4) {
        const int jn = j + 32;
        // Prefetch next step (independent of current FMAs -> issues early)
        #pragma unroll
        for (int r = 0; r < R; r++)
            wn[r] = (jn < c4) ? Wr[r][jn] : f4z;
        const float4 xv = sx[j];
        #pragma unroll
        for (int r = 0; r < R; r++) {
            acc[r] = fmaf(w[r].x, xv.x, acc[r]);
            acc[r] = fmaf(w[r].y, xv.y, acc[r]);
            acc[r] = fmaf(w[r].z, xv.z, acc[r]);
            acc[r] = fmaf(w[r].w, xv.w, acc[r]);
        }
        #pragma unroll
        for (int r = 0; r < R; r++) w[r] = wn[r];
        j = jn;
    }

    #pragma unroll
    for (int r = 0; r < R; r++) {
        float a = acc[r];
        #pragma unroll
        for (int o = 16; o; o >>= 1) a += __shfl_xor_sync(0xffffffffu, a, o);
        if (lane == 0) {
            const int row = warp + r * nw;
            float v = a + b[row];
            if (act) v = fmaxf(v, 0.f);
            y[row] = v;
        }
    }
}

extern __shared__ float4 smem_x[];

// K1: build branch input in smem, then l1/l3 GEMV (relu). blockIdx.y = branch.
__global__ void k1_input_gemv(const float* __restrict__ si,
                              const float* __restrict__ oi,
                              const float* __restrict__ ds,
                              const float* __restrict__ dob,
                              const float* __restrict__ le,
                              const float* __restrict__ J,
                              const float* __restrict__ l1W,
                              const float* __restrict__ l1b,
                              const float* __restrict__ l3W,
                              const float* __restrict__ l3b) {
    const int br = blockIdx.y;
    float* s = (float*)smem_x;
    for (int i = threadIdx.x; i < IN1; i += blockDim.x) {
        float v;
        if (i < 32)       v = br ? oi[i]       : si[i];
        else if (i < 64)  v = br ? dob[i - 32] : ds[i - 32];
        else if (i < 96)  v = le[i - 64];
        else              v = J[i - 96];
        s[i] = v;
    }
    __syncthreads();
    gemv_core<4>(br ? l3W : l1W, br ? l3b : l1b, br ? g_l3 : g_l1,
                 IN1 / 4, 1, smem_x);
}

// K2: 4-segment GEMV (gi1, gh1, gi2, gh2). blockIdx.y = segment.
struct Seg { const float *W, *x, *b; float* y; int c4; };
struct Segs4 { Seg s[4]; };

__global__ void k2_gru_gemv(Segs4 segs) {
    Seg s = segs.s[blockIdx.y];
    const float4* __restrict__ xv = (const float4*)s.x;
    for (int j = threadIdx.x; j < s.c4; j += blockDim.x) smem_x[j] = xv[j];
    __syncthreads();
    gemv_core<4>(s.W, s.b, s.y, s.c4, 0, smem_x);
}

// K3: each block computes full GRU h (2048) from gi/gh/hn into smem, then
// hidden = relu(W1 @ h + b1). blockIdx.y = branch.
__global__ void k3_gate_gemv(const float* __restrict__ hn1,
                             const float* __restrict__ hn2,
                             const float* __restrict__ l2W1,
                             const float* __restrict__ l2b1,
                             const float* __restrict__ l4W1,
                             const float* __restrict__ l4b1) {
    const int br = blockIdx.y;
    const float* __restrict__ gi = br ? g_gi2 : g_gi1;
    const float* __restrict__ gh = br ? g_gh2 : g_gh1;
    const float* __restrict__ hp = br ? hn2 : hn1;
    float* s = (float*)smem_x;
    for (int k = threadIdx.x; k < HID; k += blockDim.x) {
        float r = 1.f / (1.f + __expf(-(gi[k]       + gh[k])));
        float z = 1.f / (1.f + __expf(-(gi[k + HID] + gh[k + HID])));
        float n = tanhf(gi[k + 2 * HID] + r * gh[k + 2 * HID]);
        s[k] = (1.f - z) * n + z * hp[k];
    }
    __syncthreads();
    gemv_core<4>(br ? l4W1 : l2W1, br ? l4b1 : l2b1, br ? g_hid2 : g_hid1,
                 HID / 4, 1, smem_x);
}

// K4: out = W2 @ hidden + b2 -> d_out. blockIdx.y = branch.
__global__ void k4_out_gemv(const float* __restrict__ l2W2,
                            const float* __restrict__ l2b2,
                            const float* __restrict__ l4W2,
                            const float* __restrict__ l4b2,
                            float* __restrict__ out) {
    const int br = blockIdx.y;
    const float* __restrict__ x = br ? g_hid2 : g_hid1;
    const float4* __restrict__ xv = (const float4*)x;
    for (int j = threadIdx.x; j < H2 / 4; j += blockDim.x) smem_x[j] = xv[j];
    __syncthreads();
    gemv_core<2>(br ? l4W2 : l2W2, br ? l4b2 : l2b2, out + br * 1024,
                 H2 / 4, 0, smem_x);
}

extern "C" void kernel_launch(void* const* d_in, const int* in_sizes, int n_in,
                              void* d_out, int out_size) {
    const float* si    = (const float*)d_in[0];
    const float* oi    = (const float*)d_in[1];
    const float* ds    = (const float*)d_in[2];
    const float* dob   = (const float*)d_in[3];
    const float* le    = (const float*)d_in[4];
    const float* J     = (const float*)d_in[5];
    const float* l1W   = (const float*)d_in[6];
    const float* l1b   = (const float*)d_in[7];
    const float* g1Wih = (const float*)d_in[8];
    const float* g1Whh = (const float*)d_in[9];
    const float* g1bih = (const float*)d_in[10];
    const float* g1bhh = (const float*)d_in[11];
    const float* l2W1  = (const float*)d_in[12];
    const float* l2b1  = (const float*)d_in[13];
    const float* l2W2  = (const float*)d_in[14];
    const float* l2b2  = (const float*)d_in[15];
    const float* l3W   = (const float*)d_in[16];
    const float* l3b   = (const float*)d_in[17];
    const float* g2Wih = (const float*)d_in[18];
    const float* g2Whh = (const float*)d_in[19];
    const float* g2bih = (const float*)d_in[20];
    const float* g2bhh = (const float*)d_in[21];
    const float* l4W1  = (const float*)d_in[22];
    const float* l4b1  = (const float*)d_in[23];
    const float* l4W2  = (const float*)d_in[24];
    const float* l4b2  = (const float*)d_in[25];
    const float* hn1   = (const float*)d_in[26];
    const float* hn2   = (const float*)d_in[27];
    float* out = (float*)d_out;

    float *p_l1, *p_l3, *p_gi1, *p_gh1, *p_gi2, *p_gh2;
    cudaGetSymbolAddress((void**)&p_l1,  g_l1);
    cudaGetSymbolAddress((void**)&p_l3,  g_l3);
    cudaGetSymbolAddress((void**)&p_gi1, g_gi1);
    cudaGetSymbolAddress((void**)&p_gh1, g_gh1);
    cudaGetSymbolAddress((void**)&p_gi2, g_gi2);
    cudaGetSymbolAddress((void**)&p_gh2, g_gh2);

    // K1: 5120 rows = 4 rows/warp * 1280 warps -> 160 blocks x 2 branches
    k1_input_gemv<<<dim3(160, 2), 256, IN1 * sizeof(float)>>>(
        si, oi, ds, dob, le, J, l1W, l1b, l3W, l3b);

    // K2: 6144 rows = 4 * 1536 warps -> 192 blocks x 4 segments
    {
        Segs4 sg;
        sg.s[0] = { g1Wih, p_l1, g1bih, p_gi1, H1 / 4 };
        sg.s[1] = { g1Whh, hn1,  g1bhh, p_gh1, HID / 4 };
        sg.s[2] = { g2Wih, p_l3, g2bih, p_gi2, H1 / 4 };
        sg.s[3] = { g2Whh, hn2,  g2bhh, p_gh2, HID / 4 };
        k2_gru_gemv<<<dim3(192, 4), 256, H1 * sizeof(float)>>>(sg);
    }

    // K3: 4096 rows = 4 * 1024 warps -> 128 blocks x 2 branches
    k3_gate_gemv<<<dim3(128, 2), 256, HID * sizeof(float)>>>(
        hn1, hn2, l2W1, l2b1, l4W1, l4b1);

    // K4: 1024 rows/branch = 2 * 512 warps -> 64 blocks x 2 branches
    k4_out_gemv<<<dim3(64, 2), 256, H2 * sizeof(float)>>>(
        l2W2, l2b2, l4W2, l4b2, out);

    (void)in_sizes; (void)n_in; (void)out_size;
}

// round 8
// speedup vs baseline: 1.1373x; 1.1373x over previous
#include <cuda_runtime.h>

// ---------------------------------------------------------------------------
// DNN_SKalmanNet_GSS — batch-1 GEMV chain, HBM-bound (~499 MB weights/pass).
// 4 launches, R1-proven inner loop (plain float4 loads, warp-per-row):
//   K1: input built in smem + l1/l3 GEMV (relu)            [~46 MB] 1280 blks
//   K2: GRU gi/gh GEMV, 4 segments                         [~352 MB] 3072 blks
//   K3: GRU gate fused into staging + W1 GEMV (relu),
//       also pre-writes bias into d_out                    [~67 MB] 1024 blks
//   K4: W2 GEMV split-K x4, atomicAdd into d_out           [~34 MB] 1024 blks
// ---------------------------------------------------------------------------

#define H1   5120
#define H2   4096
#define HID  2048
#define IN1  1120

__device__ float g_l1[H1];
__device__ float g_l3[H1];
__device__ float g_gi1[3 * HID];
__device__ float g_gh1[3 * HID];
__device__ float g_gi2[3 * HID];
__device__ float g_gh2[3 * HID];
__device__ float g_hid1[H2];
__device__ float g_hid2[H2];

// Warp-per-row GEMV; x staged in smem as float4. (R1-proven loop.)
__device__ __forceinline__ void gemv_core(const float* __restrict__ W,
                                          const float* __restrict__ b,
                                          float* __restrict__ y,
                                          int rows, int c4, int act,
                                          const float4* __restrict__ sx) {
    const int lane = threadIdx.x & 31;
    const int warp = (blockIdx.x * blockDim.x + threadIdx.x) >> 5;
    const int nw   = (gridDim.x * blockDim.x) >> 5;
    for (int row = warp; row < rows; row += nw) {
        const float4* __restrict__ Wr = (const float4*)W + (size_t)row * c4;
        float acc = 0.f;
        #pragma unroll 4
        for (int j = lane; j < c4; j += 32) {
            float4 w = Wr[j];
            float4 x = sx[j];
            acc = fmaf(w.x, x.x, acc);
            acc = fmaf(w.y, x.y, acc);
            acc = fmaf(w.z, x.z, acc);
            acc = fmaf(w.w, x.w, acc);
        }
        #pragma unroll
        for (int o = 16; o; o >>= 1) acc += __shfl_xor_sync(0xffffffffu, acc, o);
        if (lane == 0) {
            float v = acc + b[row];
            if (act) v = fmaxf(v, 0.f);
            y[row] = v;
        }
    }
}

extern __shared__ float4 smem_x[];

// K1: build branch input in smem, then l1/l3 GEMV (relu). blockIdx.y = branch.
__global__ void k1_input_gemv(const float* __restrict__ si,
                              const float* __restrict__ oi,
                              const float* __restrict__ ds,
                              const float* __restrict__ dob,
                              const float* __restrict__ le,
                              const float* __restrict__ J,
                              const float* __restrict__ l1W,
                              const float* __restrict__ l1b,
                              const float* __restrict__ l3W,
                              const float* __restrict__ l3b) {
    const int br = blockIdx.y;
    float* s = (float*)smem_x;
    for (int i = threadIdx.x; i < IN1; i += blockDim.x) {
        float v;
        if (i < 32)       v = br ? oi[i]       : si[i];
        else if (i < 64)  v = br ? dob[i - 32] : ds[i - 32];
        else if (i < 96)  v = le[i - 64];
        else              v = J[i - 96];
        s[i] = v;
    }
    __syncthreads();
    gemv_core(br ? l3W : l1W, br ? l3b : l1b, br ? g_l3 : g_l1,
              H1, IN1 / 4, 1, smem_x);
}

// K2: 4-segment GEMV (gi1, gh1, gi2, gh2). blockIdx.y = segment.
struct Seg { const float *W, *x, *b; float* y; int c4; };
struct Segs4 { Seg s[4]; };

__global__ void k2_gru_gemv(Segs4 segs) {
    Seg s = segs.s[blockIdx.y];
    const float4* __restrict__ xv = (const float4*)s.x;
    for (int j = threadIdx.x; j < s.c4; j += blockDim.x) smem_x[j] = xv[j];
    __syncthreads();
    gemv_core(s.W, s.b, s.y, 3 * HID, s.c4, 0, smem_x);
}

// K3: each block computes full GRU h (2048) from gi/gh/hn into smem, then
// hidden = relu(W1 @ h + b1). blockIdx.y = branch.
// Blocks with blockIdx.x == 0 additionally pre-write the output bias b2 into
// d_out so K4 can atomicAdd split-K partials on top.
__global__ void k3_gate_gemv(const float* __restrict__ hn1,
                             const float* __restrict__ hn2,
                             const float* __restrict__ l2W1,
                             const float* __restrict__ l2b1,
                             const float* __restrict__ l4W1,
                             const float* __restrict__ l4b1,
                             const float* __restrict__ l2b2,
                             const float* __restrict__ l4b2,
                             float* __restrict__ out) {
    const int br = blockIdx.y;
    if (blockIdx.x == 0) {
        const float* b2 = br ? l4b2 : l2b2;
        for (int i = threadIdx.x; i < 1024; i += blockDim.x)
            out[br * 1024 + i] = b2[i];
    }
    const float* __restrict__ gi = br ? g_gi2 : g_gi1;
    const float* __restrict__ gh = br ? g_gh2 : g_gh1;
    const float* __restrict__ hp = br ? hn2 : hn1;
    float* s = (float*)smem_x;
    for (int k = threadIdx.x; k < HID; k += blockDim.x) {
        float r = 1.f / (1.f + __expf(-(gi[k]       + gh[k])));
        float z = 1.f / (1.f + __expf(-(gi[k + HID] + gh[k + HID])));
        float n = tanhf(gi[k + 2 * HID] + r * gh[k + 2 * HID]);
        s[k] = (1.f - z) * n + z * hp[k];
    }
    __syncthreads();
    gemv_core(br ? l4W1 : l2W1, br ? l4b1 : l2b1, br ? g_hid2 : g_hid1,
              H2, HID / 4, 1, smem_x);
}

// K4: split-K output GEMV. blockIdx.y in [0,8): br = y>>2, chunk q = y&3.
// Each block: 8 warps handle 8 rows over column chunk q (1024 cols).
// Partial dot -> atomicAdd into out (bias pre-written by K3).
#define CHUNK4 (H2 / 4 / 4)   // 256 float4 per chunk

__global__ void k4_out_gemv(const float* __restrict__ l2W2,
                            const float* __restrict__ l4W2,
                            float* __restrict__ out) {
    const int br = blockIdx.y >> 2;
    const int q  = blockIdx.y & 3;
    const float* __restrict__ W = br ? l4W2 : l2W2;
    const float* __restrict__ x = br ? g_hid2 : g_hid1;

    // Stage this chunk's x quarter (1024 floats) in smem
    const float4* __restrict__ xv = (const float4*)x + q * CHUNK4;
    for (int j = threadIdx.x; j < CHUNK4; j += blockDim.x) smem_x[j] = xv[j];
    __syncthreads();

    const int lane = threadIdx.x & 31;
    const int row  = blockIdx.x * 8 + (threadIdx.x >> 5);   // 128 blocks * 8
    const float4* __restrict__ Wr =
        (const float4*)W + (size_t)row * (H2 / 4) + q * CHUNK4;
    float acc = 0.f;
    #pragma unroll 4
    for (int j = lane; j < CHUNK4; j += 32) {
        float4 w = Wr[j];
        float4 xx = smem_x[j];
        acc = fmaf(w.x, xx.x, acc);
        acc = fmaf(w.y, xx.y, acc);
        acc = fmaf(w.z, xx.z, acc);
        acc = fmaf(w.w, xx.w, acc);
    }
    #pragma unroll
    for (int o = 16; o; o >>= 1) acc += __shfl_xor_sync(0xffffffffu, acc, o);
    if (lane == 0) atomicAdd(&out[br * 1024 + row], acc);
}

extern "C" void kernel_launch(void* const* d_in, const int* in_sizes, int n_in,
                              void* d_out, int out_size) {
    const float* si    = (const float*)d_in[0];
    const float* oi    = (const float*)d_in[1];
    const float* ds    = (const float*)d_in[2];
    const float* dob   = (const float*)d_in[3];
    const float* le    = (const float*)d_in[4];
    const float* J     = (const float*)d_in[5];
    const float* l1W   = (const float*)d_in[6];
    const float* l1b   = (const float*)d_in[7];
    const float* g1Wih = (const float*)d_in[8];
    const float* g1Whh = (const float*)d_in[9];
    const float* g1bih = (const float*)d_in[10];
    const float* g1bhh = (const float*)d_in[11];
    const float* l2W1  = (const float*)d_in[12];
    const float* l2b1  = (const float*)d_in[13];
    const float* l2W2  = (const float*)d_in[14];
    const float* l2b2  = (const float*)d_in[15];
    const float* l3W   = (const float*)d_in[16];
    const float* l3b   = (const float*)d_in[17];
    const float* g2Wih = (const float*)d_in[18];
    const float* g2Whh = (const float*)d_in[19];
    const float* g2bih = (const float*)d_in[20];
    const float* g2bhh = (const float*)d_in[21];
    const float* l4W1  = (const float*)d_in[22];
    const float* l4b1  = (const float*)d_in[23];
    const float* l4W2  = (const float*)d_in[24];
    const float* l4b2  = (const float*)d_in[25];
    const float* hn1   = (const float*)d_in[26];
    const float* hn2   = (const float*)d_in[27];
    float* out = (float*)d_out;

    float *p_l1, *p_l3, *p_gi1, *p_gh1, *p_gi2, *p_gh2;
    cudaGetSymbolAddress((void**)&p_l1,  g_l1);
    cudaGetSymbolAddress((void**)&p_l3,  g_l3);
    cudaGetSymbolAddress((void**)&p_gi1, g_gi1);
    cudaGetSymbolAddress((void**)&p_gh1, g_gh1);
    cudaGetSymbolAddress((void**)&p_gi2, g_gi2);
    cudaGetSymbolAddress((void**)&p_gh2, g_gh2);

    // K1: 5120 rows / 8 warps -> 640 blocks x 2 branches
    k1_input_gemv<<<dim3(H1 / 8, 2), 256, IN1 * sizeof(float)>>>(
        si, oi, ds, dob, le, J, l1W, l1b, l3W, l3b);

    // K2: 6144 rows / 8 warps -> 768 blocks x 4 segments
    {
        Segs4 sg;
        sg.s[0] = { g1Wih, p_l1, g1bih, p_gi1, H1 / 4 };
        sg.s[1] = { g1Whh, hn1,  g1bhh, p_gh1, HID / 4 };
        sg.s[2] = { g2Wih, p_l3, g2bih, p_gi2, H1 / 4 };
        sg.s[3] = { g2Whh, hn2,  g2bhh, p_gh2, HID / 4 };
        k2_gru_gemv<<<dim3((3 * HID) / 8, 4), 256, H1 * sizeof(float)>>>(sg);
    }

    // K3: 4096 rows / 8 warps -> 512 blocks x 2 branches (also bias->out)
    k3_gate_gemv<<<dim3(H2 / 8, 2), 256, HID * sizeof(float)>>>(
        hn1, hn2, l2W1, l2b1, l4W1, l4b1, l2b2, l4b2, out);

    // K4: 1024 rows / 8 warps = 128 blocks x (2 branches * 4 col-chunks)
    k4_out_gemv<<<dim3(128, 8), 256, CHUNK4 * sizeof(float4)>>>(
        l2W2, l4W2, out);

    (void)in_sizes; (void)n_in; (void)out_size;
}